// round 5
// baseline (speedup 1.0000x reference)
#include <cuda_runtime.h>
#include <stdint.h>

#define NROW 16384
#define KC 64
#define NCHUNK (NROW / KC)            /* 256 */
#define STG 3
#define HALF_STAGE 32768u             /* A (or B) per stage: 128 x 64 fp32 */
#define STAGE_BYTES 65536u
#define BIG_SMEM (STG * STAGE_BYTES)  /* 196608 */
#define PREP_SMEM ((64 * 64 + 128 * 132) * 4)

__device__ float g_Tt[128 * NROW];    /* B operand, K-major, tf32-rounded */
__device__ float g_X[NROW * 128];     /* layer activations */

__device__ __forceinline__ float eluf(float x) { return x > 0.f ? x : expm1f(x); }
__device__ __forceinline__ uint32_t swz(uint32_t x) { return x ^ ((x >> 3) & 0x70); }

__device__ __forceinline__ uint32_t smem_u32(const void* p) {
    uint32_t a;
    asm("{ .reg .u64 t; cvta.to.shared.u64 t, %1; cvt.u32.u64 %0, t; }" : "=r"(a) : "l"(p));
    return a;
}
__device__ __forceinline__ void cp_async16(uint32_t dst, const void* src) {
    asm volatile("cp.async.cg.shared.global [%0], [%1], 16;" :: "r"(dst), "l"(src) : "memory");
}
__device__ __forceinline__ void ldsm_x4(uint32_t* r, uint32_t addr) {
    asm volatile("ldmatrix.sync.aligned.m8n8.x4.shared.b16 {%0,%1,%2,%3}, [%4];"
                 : "=r"(r[0]), "=r"(r[1]), "=r"(r[2]), "=r"(r[3]) : "r"(addr));
}
__device__ __forceinline__ void mma_tf32(float* c, const uint32_t* a, const uint32_t* b) {
    asm volatile(
        "mma.sync.aligned.m16n8k8.row.col.f32.tf32.tf32.f32 "
        "{%0,%1,%2,%3}, {%4,%5,%6,%7}, {%8,%9}, {%0,%1,%2,%3};"
        : "+f"(c[0]), "+f"(c[1]), "+f"(c[2]), "+f"(c[3])
        : "r"(a[0]), "r"(a[1]), "r"(a[2]), "r"(a[3]), "r"(b[0]), "r"(b[1]));
}
__device__ __forceinline__ float tf32r(float x) {
    uint32_t u;
    asm("cvt.rna.tf32.f32 %0, %1;" : "=r"(u) : "f"(x));
    return __uint_as_float(u);
}

/* Tt[j][k] = sum_d f(src[k][d(+64)]) * W[d][j&63]; output tf32-rounded */
__global__ __launch_bounds__(512) void gcn_prep(const float* __restrict__ Xin,
                                                const float* __restrict__ W,
                                                int apply_elu, int use_gx) {
    extern __shared__ float sm[];
    float* sW = sm;
    float* sXT = sm + 64 * 64;
    const float* src = use_gx ? (const float*)g_X : Xin;
    int tid = threadIdx.x;
    int k0 = blockIdx.x * 128;

    for (int l = tid; l < 64 * 64; l += 512) sW[l] = W[l];
    #pragma unroll
    for (int it = 0; it < 32; ++it) {
        int l = it * 512 + tid;
        int k = l >> 7, d = l & 127;
        float v = src[(size_t)(k0 + k) * 128 + d];
        if (apply_elu) v = eluf(v);
        sXT[d * 132 + k] = v;
    }
    __syncthreads();

    int warp = tid >> 5, lane = tid & 31;
    int k = lane * 4;
    for (int jp = warp; jp < 64; jp += 16) {
        float4 a0 = make_float4(0.f, 0.f, 0.f, 0.f);
        float4 a1 = make_float4(0.f, 0.f, 0.f, 0.f);
        #pragma unroll 16
        for (int d = 0; d < 64; ++d) {
            float w = sW[d * 64 + jp];
            float4 xs = *(const float4*)&sXT[d * 132 + k];
            float4 xu = *(const float4*)&sXT[(64 + d) * 132 + k];
            a0.x = fmaf(xs.x, w, a0.x); a0.y = fmaf(xs.y, w, a0.y);
            a0.z = fmaf(xs.z, w, a0.z); a0.w = fmaf(xs.w, w, a0.w);
            a1.x = fmaf(xu.x, w, a1.x); a1.y = fmaf(xu.y, w, a1.y);
            a1.z = fmaf(xu.z, w, a1.z); a1.w = fmaf(xu.w, w, a1.w);
        }
        a0.x = tf32r(a0.x); a0.y = tf32r(a0.y); a0.z = tf32r(a0.z); a0.w = tf32r(a0.w);
        a1.x = tf32r(a1.x); a1.y = tf32r(a1.y); a1.z = tf32r(a1.z); a1.w = tf32r(a1.w);
        *(float4*)&g_Tt[(size_t)jp * NROW + k0 + k] = a0;
        *(float4*)&g_Tt[(size_t)(jp + 64) * NROW + k0 + k] = a1;
    }
}

/* g_X[m][n] = elu( sum_k adj[m][k] * Tt[n][k] + bias[n&63] ), mma.sync tf32 */
__global__ __launch_bounds__(256, 1) void gcn_big(const float* __restrict__ adj,
                                                  const float* __restrict__ bias) {
    extern __shared__ char dsm[];
    uint32_t sb = smem_u32(dsm);
    int tid = threadIdx.x;
    int lane = tid & 31, wid = tid >> 5;
    int wm = wid & 3, wn = wid >> 2;      /* warp tile: 32(m) x 64(n) */
    int m0 = blockIdx.x * 128;
    int grp = lane >> 3, li = lane & 7;

    float acc[2][8][4];
    #pragma unroll
    for (int i = 0; i < 2; ++i)
        #pragma unroll
        for (int j = 0; j < 8; ++j)
            #pragma unroll
            for (int r = 0; r < 4; ++r) acc[i][j][r] = 0.f;

    const float* gA = adj + (size_t)m0 * NROW;
    const float* gB = g_Tt;

    /* precomputed fragment smem offsets (segs 0..3 of a 16KB block);
       segs 4..7 reached via XOR 64 (valid because swz(x+64) == swz(x)^64) */
    uint32_t aOff[2][2], bOff[4][2];
    #pragma unroll
    for (int mi = 0; mi < 2; ++mi) {
        int rowa = wm * 32 + mi * 16 + ((grp & 1) << 3) + li;
        #pragma unroll
        for (int ts = 0; ts < 2; ++ts) {
            int seg = ts * 2 + (grp >> 1);
            aOff[mi][ts] = swz((uint32_t)(rowa * 128 + seg * 16));
        }
    }
    #pragma unroll
    for (int p = 0; p < 4; ++p) {
        int rowb = wn * 64 + p * 16 + ((grp >> 1) << 3) + li;
        #pragma unroll
        for (int ts = 0; ts < 2; ++ts) {
            int seg = ts * 2 + (grp & 1);
            bOff[p][ts] = swz((uint32_t)(rowb * 128 + seg * 16));
        }
    }

#define LOAD_STAGE(ii) do {                                                     \
    uint32_t st_ = sb + (uint32_t)((ii) % STG) * STAGE_BYTES;                   \
    int k0_ = (ii) * KC;                                                        \
    _Pragma("unroll")                                                           \
    for (int j_ = 0; j_ < 8; ++j_) {                                            \
        int v_ = j_ * 256 + tid;                                                \
        int blk_ = v_ >> 10;                                                    \
        int row_ = (v_ >> 3) & 127;                                             \
        int seg_ = v_ & 7;                                                      \
        uint32_t off_ = (uint32_t)(blk_ * 16384) +                              \
                        swz((uint32_t)(row_ * 128 + seg_ * 16));                \
        size_t go_ = (size_t)row_ * NROW + k0_ + blk_ * 32 + seg_ * 4;          \
        cp_async16(st_ + off_, gA + go_);                                       \
        cp_async16(st_ + HALF_STAGE + off_, gB + go_);                          \
    }                                                                           \
    asm volatile("cp.async.commit_group;" ::: "memory");                        \
} while (0)

/* load fragments for k-step t (0..7) of current stage into buffer bb */
#define LOAD_FRAGS(bb, t) do {                                                  \
    uint32_t base_ = (uint32_t)(((t) >> 2) * 16384);                            \
    int ts_ = (t) & 3;                                                          \
    uint32_t hx_ = (uint32_t)((ts_ >> 1) * 64);                                 \
    int q_ = ts_ & 1;                                                           \
    _Pragma("unroll")                                                           \
    for (int mi_ = 0; mi_ < 2; ++mi_)                                           \
        ldsm_x4(af[bb][mi_], sA + base_ + (aOff[mi_][q_] ^ hx_));               \
    _Pragma("unroll")                                                           \
    for (int mi_ = 0; mi_ < 2; ++mi_)                                           \
        _Pragma("unroll")                                                       \
        for (int r_ = 0; r_ < 4; ++r_)                                          \
            asm("cvt.rna.tf32.f32 %0, %0;" : "+r"(af[bb][mi_][r_]));            \
    _Pragma("unroll")                                                           \
    for (int p_ = 0; p_ < 4; ++p_) {                                            \
        uint32_t r4_[4];                                                        \
        ldsm_x4(r4_, sB + base_ + (bOff[p_][q_] ^ hx_));                        \
        bf[bb][2 * p_][0] = r4_[0]; bf[bb][2 * p_][1] = r4_[1];                 \
        bf[bb][2 * p_ + 1][0] = r4_[2]; bf[bb][2 * p_ + 1][1] = r4_[3];         \
    }                                                                           \
} while (0)

    LOAD_STAGE(0); LOAD_STAGE(1);

    uint32_t af[2][2][4], bf[2][8][2];

    #pragma unroll 1
    for (int i = 0; i < NCHUNK; ++i) {
        asm volatile("cp.async.wait_group 1;" ::: "memory");
        __syncthreads();
        if (i + 2 < NCHUNK) LOAD_STAGE(i + 2);
        else asm volatile("cp.async.commit_group;" ::: "memory");
        uint32_t sA = sb + (uint32_t)(i % STG) * STAGE_BYTES;
        uint32_t sB = sA + HALF_STAGE;
        LOAD_FRAGS(0, 0);
        #pragma unroll
        for (int t = 0; t < 8; ++t) {
            if (t < 7) LOAD_FRAGS((t + 1) & 1, t + 1);
            int cur = t & 1;
            #pragma unroll
            for (int mi = 0; mi < 2; ++mi)
                #pragma unroll
                for (int ni = 0; ni < 8; ++ni)
                    mma_tf32(acc[mi][ni], af[cur][mi], bf[cur][ni]);
        }
    }
    asm volatile("cp.async.wait_group 0;" ::: "memory");

    /* epilogue: bias + elu, direct fragment store (8B vectors) */
    int col0 = wn * 64 + (lane & 3) * 2;
    int rbase = m0 + wm * 32 + (lane >> 2);
    #pragma unroll
    for (int mi = 0; mi < 2; ++mi)
        #pragma unroll
        for (int ni = 0; ni < 8; ++ni) {
            int col = col0 + ni * 8;
            float b0v = bias[col & 63], b1v = bias[(col + 1) & 63];
            int rlo = rbase + mi * 16;
            float2 v0 = make_float2(eluf(acc[mi][ni][0] + b0v), eluf(acc[mi][ni][1] + b1v));
            float2 v1 = make_float2(eluf(acc[mi][ni][2] + b0v), eluf(acc[mi][ni][3] + b1v));
            *(float2*)&g_X[(size_t)rlo * 128 + col] = v0;
            *(float2*)&g_X[(size_t)(rlo + 8) * 128 + col] = v1;
        }
#undef LOAD_STAGE
#undef LOAD_FRAGS
}

/* out[k][o] = sum_j g_X[k][j] * Wl[o][j] + bl[o] */
__global__ __launch_bounds__(256) void gcn_final(const float* __restrict__ Wl,
                                                 const float* __restrict__ bl,
                                                 float* __restrict__ out) {
    __shared__ float sWlT[128 * 32];
    int tid = threadIdx.x;
    for (int l = tid; l < 4096; l += 256) {
        int o = l >> 7, j = l & 127;
        sWlT[j * 32 + o] = Wl[l];
    }
    __syncthreads();
    int warp = tid >> 5, lane = tid & 31;
    int k0 = blockIdx.x * 128;
    float b = bl[lane];
    for (int r = warp; r < 128; r += 8) {
        const float* yrow = g_X + (size_t)(k0 + r) * 128;
        float acc = b;
        #pragma unroll 16
        for (int j = 0; j < 128; ++j)
            acc = fmaf(__ldg(&yrow[j]), sWlT[j * 32 + lane], acc);
        out[(size_t)(k0 + r) * 32 + lane] = acc;
    }
}

extern "C" void kernel_launch(void* const* d_in, const int* in_sizes, int n_in,
                              void* d_out, int out_size) {
    const float* z   = (const float*)d_in[0];
    const float* adj = (const float*)d_in[1];
    const float* W0  = (const float*)d_in[2];
    const float* b0  = (const float*)d_in[3];
    const float* W1  = (const float*)d_in[4];
    const float* b1  = (const float*)d_in[5];
    const float* Wl  = (const float*)d_in[6];
    const float* bl  = (const float*)d_in[7];
    float* out = (float*)d_out;

    cudaFuncSetAttribute(gcn_prep, cudaFuncAttributeMaxDynamicSharedMemorySize, PREP_SMEM);
    cudaFuncSetAttribute(gcn_big,  cudaFuncAttributeMaxDynamicSharedMemorySize, BIG_SMEM);

    gcn_prep<<<128, 512, PREP_SMEM>>>(z, W0, 1, 0);
    gcn_big <<<128, 256, BIG_SMEM>>>(adj, b0);
    gcn_prep<<<128, 512, PREP_SMEM>>>(z, W1, 0, 1);
    gcn_big <<<128, 256, BIG_SMEM>>>(adj, b1);
    gcn_final<<<128, 256>>>(Wl, bl, out);
}